// round 12
// baseline (speedup 1.0000x reference)
#include <cuda_runtime.h>

// add_ResnetBlock_77360950935559
//
// Reference:
//   out = 0.1 * relu(adder2d(relu(adder2d(x, w1)), w2)) + x
// where adder2d(x, w) = -sum |patch - w|  (AdderNet, -cdist L1).
//
// Identity: adder2d output is strictly negative everywhere (sum of 576 abs
// terms of continuous random values is > 0, including zero-padded border
// positions since |0 - w| > 0). Hence relu(adder2d(.)) == 0.0f identically,
// and out = 0.1f * 0.0f + x = x, BITWISE equal to the input in fp32.
// Verified: rounds 1-3 all measured rel_err == 0.0 exactly; identity is
// seed-independent (measure-one over continuous random inputs).
//
// Round 3 established: CE memcpy node (4.6us) >> SM copy kernel (22us wall,
// DVFS-throttled in the replay loop). This round (ninth submission; eight
// prior attempts hit broker GPUAcquisitionTimeout, never measured): split
// the copy into two halves on forked streams so the graph can run the two
// memcpy nodes on two copy engines concurrently, halving the transfer
// portion of each replay.
//
// The fork/join uses capture-legal cudaEventRecord/cudaStreamWaitEvent.
// Stream/events are created once, lazily, on the FIRST call — which the
// harness makes uncaptured (correctness pass) before graph capture — so no
// resource creation occurs inside capture. No device memory is allocated.

extern "C" void kernel_launch(void* const* d_in, const int* in_sizes, int n_in,
                              void* d_out, int out_size)
{
    static cudaStream_t s1 = nullptr;
    static cudaEvent_t  e_fork = nullptr, e_join = nullptr;
    if (s1 == nullptr) cudaStreamCreateWithFlags(&s1, cudaStreamNonBlocking);
    if (e_fork == nullptr) cudaEventCreateWithFlags(&e_fork, cudaEventDisableTiming);
    if (e_join == nullptr) cudaEventCreateWithFlags(&e_join, cudaEventDisableTiming);

    const char* src = (const char*)d_in[0];
    char*       dst = (char*)d_out;
    size_t bytes = (size_t)out_size * sizeof(float);   // 1.6 MB
    size_t half  = bytes / 2;

    // Fork: second half on side stream (separate CE), first half on stream 0.
    cudaEventRecord(e_fork, 0);
    cudaStreamWaitEvent(s1, e_fork, 0);
    cudaMemcpyAsync(dst + half, src + half, bytes - half,
                    cudaMemcpyDeviceToDevice, s1);
    cudaMemcpyAsync(dst, src, half, cudaMemcpyDeviceToDevice, 0);
    // Join back into the capture stream.
    cudaEventRecord(e_join, s1);
    cudaStreamWaitEvent(0, e_join, 0);
}